// round 15
// baseline (speedup 1.0000x reference)
#include <cuda_runtime.h>

#define NN    256
#define TT    512    // gnn CTA threads
#define FIN   6
#define HD    32
#define VECD  26
#define DPI   512
#define BB    1024
#define EMAX  2304
#define EMAXP 2568   // even-padded capacity + zero slots
#define PADJ  2564   // even pair index at guaranteed-zero edges
#define ST    36     // padded row stride (floats)

__device__ int g_degO[NN];
__device__ int g_degI[NN];
__device__ int g_rowptr[NN + 1];
__device__ int g_perm[NN];
__device__ __align__(16) float2 g_edge[EMAXP];
__device__ float g_comb[BB * 64];

// ---------------------------------------------------------------------------
// packed f32x2 helpers
// ---------------------------------------------------------------------------
__device__ __forceinline__ unsigned long long dup2(float v) {
    unsigned long long r;
    asm("mov.b64 %0, {%1, %1};" : "=l"(r) : "f"(v));
    return r;
}
__device__ __forceinline__ unsigned long long pack2(float lo, float hi) {
    unsigned long long r;
    asm("mov.b64 %0, {%1, %2};" : "=l"(r) : "f"(lo), "f"(hi));
    return r;
}
__device__ __forceinline__ void ffma2(unsigned long long& a, unsigned long long x,
                                      unsigned long long y) {
    asm("fma.rn.f32x2 %0, %1, %2, %0;" : "+l"(a) : "l"(x), "l"(y));
}
__device__ __forceinline__ void unpack2(float& lo, float& hi, unsigned long long v) {
    asm("mov.b64 {%0, %1}, %2;" : "=f"(lo), "=f"(hi) : "l"(v));
}

// ---------------------------------------------------------------------------
// prep1: multi-CTA degree histogram (spread global atomics).
// ---------------------------------------------------------------------------
__global__ void prep1_kernel(const int* __restrict__ src, const int* __restrict__ dst, int E) {
    int e = blockIdx.x * blockDim.x + threadIdx.x;
    if (e < E) {
        atomicAdd(&g_degO[src[e]], 1);
        atomicAdd(&g_degI[dst[e]], 1);
    }
}

// ---------------------------------------------------------------------------
// prep2: scan, norms, scatter CSR, counting-sort nodes by padded degree.
// Triggers PDL immediately so gnn can stage weights/gf concurrently.
// ---------------------------------------------------------------------------
__global__ void prep2_kernel(const int* __restrict__ src, const int* __restrict__ dst, int E) {
    cudaTriggerProgrammaticLaunchCompletion();
    __shared__ float sO[NN], sI[NN];
    __shared__ int cur[NN];
    __shared__ int wsum[8];
    __shared__ int cnt[128];
    int t = threadIdx.x, lane = t & 31, w = t >> 5;
    int dO = g_degO[t], dI = g_degI[t];
    int dp = (dI + 1) & ~1;
    if (t < 128) cnt[t] = 0;
    int v = dp;
#pragma unroll
    for (int o = 1; o < 32; o <<= 1) {
        int nv_ = __shfl_up_sync(0xffffffffu, v, o);
        if (lane >= o) v += nv_;
    }
    if (lane == 31) wsum[w] = v;
    __syncthreads();
    if (t == 0) {
        int acc = 0;
#pragma unroll
        for (int i = 0; i < 8; i++) { acc += wsum[i]; wsum[i] = acc; }
    }
    int bin = dp >> 1; if (bin > 127) bin = 127;
    atomicAdd(&cnt[bin], 1);
    __syncthreads();
    int excl = (w ? wsum[w - 1] : 0) + v - dp;
    g_rowptr[t] = excl;
    cur[t] = excl;
    if (t == NN - 1) g_rowptr[NN] = excl + dp;
    sO[t] = dO ? rsqrtf((float)dO) : 0.f;
    sI[t] = dI ? rsqrtf((float)dI) : 0.f;
    if (t < 32) {
        int c0 = cnt[t*4], c1 = cnt[t*4+1], c2 = cnt[t*4+2], c3 = cnt[t*4+3];
        int tot = c0 + c1 + c2 + c3;
        int sc = tot;
#pragma unroll
        for (int o = 1; o < 32; o <<= 1) {
            int nv_ = __shfl_up_sync(0xffffffffu, sc, o);
            if (lane >= o) sc += nv_;
        }
        int base = sc - tot;
        cnt[t*4]   = base;
        cnt[t*4+1] = base + c0;
        cnt[t*4+2] = base + c0 + c1;
        cnt[t*4+3] = base + c0 + c1 + c2;
    }
    __syncthreads();
    int pos = atomicAdd(&cnt[bin], 1);
    g_perm[pos] = t;
    for (int e = t; e < E; e += NN) {
        int s_ = src[e], d_ = dst[e];
        float nv = sO[s_] * sI[d_];
        int p2 = atomicAdd(&cur[d_], 1);
        g_edge[p2] = make_float2(__int_as_float(s_ * ST), nv);
    }
    if (dI & 1) g_edge[excl + dI] = make_float2(__int_as_float(0), 0.f);
    if (t < 8) g_edge[2560 + t] = make_float2(__int_as_float(0), 0.f);
    g_degO[t] = 0;
    g_degI[t] = 0;
}

// ---------------------------------------------------------------------------
// Octet gather over degree-sorted pairs, edge prefetch pipeline.
// Anti-correlated scheduling: thread handles pairs p and 127-p, so every
// thread's degree total is ~constant -> minimal barrier skew.
// ---------------------------------------------------------------------------
template <int POOL>
__device__ __forceinline__ void gatherO(const float* __restrict__ bufS,
                                        float* __restrict__ bufD,
                                        const float* __restrict__ sEf,
                                        const int* __restrict__ srow,
                                        const int* __restrict__ sperm,
                                        const float* __restrict__ sbias,
                                        float* __restrict__ pool, int t)
{
    int l = t & 31, w = t >> 5;
    int o = l >> 3, q = l & 7;
    const float* bufq = bufS + 4 * q;
    float4 bv = *(const float4*)(sbias + 4 * q);
    float4 ps = make_float4(0.f, 0.f, 0.f, 0.f);
    int pbase = w * 4 + o;
#pragma unroll
    for (int pp = 0; pp < 2; pp++) {
        int pair = pp ? (127 - pbase) : pbase;
        int nA = sperm[2 * pair], nB = sperm[2 * pair + 1];
        int jA = srow[nA], eA = srow[nA + 1];
        int jB = srow[nB], eB = srow[nB + 1];
        unsigned long long a0 = 0, a1 = 0, a2 = 0, a3 = 0;
        unsigned long long c0 = 0, c1 = 0, c2 = 0, c3 = 0;
        int iA = jA < eA ? jA : PADJ;
        int iB = jB < eB ? jB : PADJ;
        float4 eA4 = *(const float4*)(sEf + 2 * iA);
        float4 eB4 = *(const float4*)(sEf + 2 * iB);
        while (jA < eA || jB < eB) {
            float4 cA = eA4, cB = eB4;
            jA += 2; jB += 2;
            iA = jA < eA ? jA : PADJ;
            iB = jB < eB ? jB : PADJ;
            eA4 = *(const float4*)(sEf + 2 * iA);
            eB4 = *(const float4*)(sEf + 2 * iB);
            ulonglong2 xA0 = *(const ulonglong2*)(bufq + __float_as_int(cA.x));
            ulonglong2 xA1 = *(const ulonglong2*)(bufq + __float_as_int(cA.z));
            ulonglong2 xB0 = *(const ulonglong2*)(bufq + __float_as_int(cB.x));
            ulonglong2 xB1 = *(const ulonglong2*)(bufq + __float_as_int(cB.z));
            unsigned long long vA0 = dup2(cA.y), vA1 = dup2(cA.w);
            unsigned long long vB0 = dup2(cB.y), vB1 = dup2(cB.w);
            ffma2(a0, vA0, xA0.x); ffma2(a1, vA0, xA0.y);
            ffma2(a2, vA1, xA1.x); ffma2(a3, vA1, xA1.y);
            ffma2(c0, vB0, xB0.x); ffma2(c1, vB0, xB0.y);
            ffma2(c2, vB1, xB1.x); ffma2(c3, vB1, xB1.y);
        }
        float r0, r1, r2, r3, s0, s1, s2, s3;
        unpack2(r0, r1, a0); unpack2(r2, r3, a1);
        unpack2(s0, s1, a2); unpack2(s2, s3, a3);
        float4 hA;
        hA.x = fmaxf(r0 + s0 + bv.x, 0.f);
        hA.y = fmaxf(r1 + s1 + bv.y, 0.f);
        hA.z = fmaxf(r2 + s2 + bv.z, 0.f);
        hA.w = fmaxf(r3 + s3 + bv.w, 0.f);
        unpack2(r0, r1, c0); unpack2(r2, r3, c1);
        unpack2(s0, s1, c2); unpack2(s2, s3, c3);
        float4 hB;
        hB.x = fmaxf(r0 + s0 + bv.x, 0.f);
        hB.y = fmaxf(r1 + s1 + bv.y, 0.f);
        hB.z = fmaxf(r2 + s2 + bv.z, 0.f);
        hB.w = fmaxf(r3 + s3 + bv.w, 0.f);
        if (POOL) {
            ps.x += hA.x + hB.x; ps.y += hA.y + hB.y;
            ps.z += hA.z + hB.z; ps.w += hA.w + hB.w;
        } else {
            *(float4*)(bufD + nA * ST + 4 * q) = hA;
            *(float4*)(bufD + nB * ST + 4 * q) = hB;
        }
    }
    if (POOL) {
#pragma unroll
        for (int m = 8; m <= 16; m <<= 1) {
            ps.x += __shfl_xor_sync(0xffffffffu, ps.x, m);
            ps.y += __shfl_xor_sync(0xffffffffu, ps.y, m);
            ps.z += __shfl_xor_sync(0xffffffffu, ps.z, m);
            ps.w += __shfl_xor_sync(0xffffffffu, ps.w, m);
        }
        if (l < 8) *(float4*)(pool + (w * 8 + q) * 4) = ps;
    }
}

// ---------------------------------------------------------------------------
// Linear: thread = (node t>>1, feature-half t&1); 16 outputs via f32x2.
// ---------------------------------------------------------------------------
__device__ __forceinline__ void linear_phase(const float* __restrict__ bufS,
                                             float* __restrict__ bufD,
                                             const float* __restrict__ W, int t)
{
    int n = t >> 1, fo = (t & 1) * 16;
    float h[HD];
    const float4* hr = (const float4*)(bufS + n * ST);
#pragma unroll
    for (int q = 0; q < 8; q++) {
        float4 v = hr[q];
        h[4*q] = v.x; h[4*q+1] = v.y; h[4*q+2] = v.z; h[4*q+3] = v.w;
    }
    unsigned long long y2[8];
#pragma unroll
    for (int q = 0; q < 8; q++) y2[q] = 0ULL;
#pragma unroll
    for (int k = 0; k < HD; k++) {
        unsigned long long hk = dup2(h[k]);
        const ulonglong2* Wr = (const ulonglong2*)(W + k * HD + fo);
#pragma unroll
        for (int q = 0; q < 4; q++) {
            ulonglong2 wv = Wr[q];
            ffma2(y2[2*q],     hk, wv.x);
            ffma2(y2[2*q + 1], hk, wv.y);
        }
    }
    ulonglong2* out = (ulonglong2*)(bufD + n * ST + fo);
#pragma unroll
    for (int q = 0; q < 4; q++) out[q] = make_ulonglong2(y2[2*q], y2[2*q+1]);
}

// ---------------------------------------------------------------------------
// Main GNN kernel: one CTA (512 threads) per batch element.
// PDL: stages weights/gf + runs phase0 BEFORE grid-dependency sync (overlaps
// prep2), then stages edge CSR after the sync.
// ---------------------------------------------------------------------------
__global__ void __launch_bounds__(TT, 2) gnn_kernel(
    const float* __restrict__ gf, const float* __restrict__ vec,
    const float* __restrict__ W1, const float* __restrict__ b1,
    const float* __restrict__ W2, const float* __restrict__ b2,
    const float* __restrict__ W3, const float* __restrict__ b3,
    const float* __restrict__ We, const float* __restrict__ be)
{
    extern __shared__ float s[];
    float* bufA = s;                         // 9216
    float* bufB = bufA + NN * ST;            // 9216
    float* sEf  = bufB + NN * ST;            // 5136
    int*   srow = (int*)(sEf + 2 * EMAXP);   // 260
    int*   sperm= srow + 260;                // 256
    float* sW1  = (float*)(sperm + 256);     // 192
    float* sW2  = sW1 + 192;                 // 1024
    float* sW3  = sW2 + 1024;                // 1024
    float* sWe  = sW3 + 1024;                // 1024
    float* sb   = sWe + 1024;                // 128
    float* pool = sb + 128;                  // 512
    float* hg   = pool + 512;                // 32

    int t = threadIdx.x;
    int b = blockIdx.x;

    // ---- pre-dependency staging: weights, biases, gf (independent of prep) ----
    {
        if (t < FIN * HD) sW1[t] = W1[t];
        for (int i = t; i < HD * HD; i += TT) {
            sW2[i] = W2[i]; sW3[i] = W3[i]; sWe[i] = We[i];
        }
        if (t < HD) { sb[t] = b1[t]; sb[32+t] = b2[t]; sb[64+t] = b3[t]; sb[96+t] = be[t]; }
        const float4* g4 = (const float4*)(gf + (size_t)b * NN * FIN);
        float4* xb = (float4*)bufB;
        if (t < NN * FIN / 4) xb[t] = g4[t];
    }
    __syncthreads();

    // ---- phase 0: t0 = x @ W1 -> bufA (node t>>1, 16 features) ----
    {
        int n = t >> 1, fo = (t & 1) * 16;
        float x[FIN];
#pragma unroll
        for (int k = 0; k < FIN; k++) x[k] = bufB[n * FIN + k];
        unsigned long long y2[8];
#pragma unroll
        for (int q = 0; q < 8; q++) y2[q] = 0ULL;
#pragma unroll
        for (int k = 0; k < FIN; k++) {
            unsigned long long xk = dup2(x[k]);
            const ulonglong2* Wr = (const ulonglong2*)(sW1 + k * HD + fo);
#pragma unroll
            for (int q = 0; q < 4; q++) {
                ulonglong2 wv = Wr[q];
                ffma2(y2[2*q], xk, wv.x);
                ffma2(y2[2*q+1], xk, wv.y);
            }
        }
        ulonglong2* row = (ulonglong2*)(bufA + n * ST + fo);
#pragma unroll
        for (int q = 0; q < 4; q++) row[q] = make_ulonglong2(y2[2*q], y2[2*q+1]);
    }

    // ---- wait for prep2, then stage CSR/perm ----
    cudaGridDependencySynchronize();
    {
        const float4* ge4 = (const float4*)g_edge;
        float4* se4 = (float4*)sEf;
        for (int i = t; i < EMAXP / 2; i += TT) se4[i] = ge4[i];
        if (t < NN) { srow[t] = g_rowptr[t]; sperm[t] = g_perm[t]; }
        if (t == 0) srow[NN] = g_rowptr[NN];
    }
    __syncthreads();

    gatherO<0>(bufA, bufB, sEf, srow, sperm, sb, pool, t);
    __syncthreads();
    linear_phase(bufB, bufA, sW2, t);
    __syncthreads();
    gatherO<0>(bufA, bufB, sEf, srow, sperm, sb + 32, pool, t);
    __syncthreads();
    linear_phase(bufB, bufA, sW3, t);
    __syncthreads();
    gatherO<1>(bufA, bufB, sEf, srow, sperm, sb + 64, pool, t);
    __syncthreads();

    // ---- finish mean pool (16 warps' partials) ----
    if (t < 8) {
        float4 sum = make_float4(0.f, 0.f, 0.f, 0.f);
#pragma unroll
        for (int w = 0; w < 16; w++) {
            float4 v = *(const float4*)(pool + (w * 8 + t) * 4);
            sum.x += v.x; sum.y += v.y; sum.z += v.z; sum.w += v.w;
        }
        const float inv = 1.f / 256.f;
        hg[4*t]   = sum.x * inv; hg[4*t+1] = sum.y * inv;
        hg[4*t+2] = sum.z * inv; hg[4*t+3] = sum.w * inv;
    }
    __syncthreads();

    if (t < HD) {
        float e = sb[96 + t];
#pragma unroll
        for (int k = 0; k < HD; k++)
            e = fmaf(hg[k], sWe[k * HD + t], e);
        g_comb[b * 64 + VECD + t] = e;
    }
    if (t >= 64 && t < 64 + VECD)
        g_comb[b * 64 + (t - 64)] = vec[(size_t)b * VECD + (t - 64)];
    cudaTriggerProgrammaticLaunchCompletion();
}

// ---------------------------------------------------------------------------
// Heads: grid 256 = 16 batch-tiles(64) x 8 col-tiles(64) x 2 heads.
// PDL: stages pre-duplicated W slice BEFORE grid-dependency sync (overlaps
// gnn tail), comb tiles after. Inner loop: 3 LDS.128 + 8 FFMA2 per k.
// ---------------------------------------------------------------------------
__global__ void __launch_bounds__(NN) heads_kernel(
    const float* __restrict__ Wpi, const float* __restrict__ bpi,
    const float* __restrict__ Wvf, const float* __restrict__ bvf,
    float* __restrict__ out)
{
    __shared__ __align__(16) unsigned long long sWd[58 * 64];  // dup'd W slice
    __shared__ __align__(16) unsigned long long sCp[58 * 32];
    __shared__ float sbias[64];

    int t = threadIdx.x;
    int bt = blockIdx.x & 15;
    int ct = (blockIdx.x >> 4) & 7;
    int head = blockIdx.x >> 7;
    const float* W = head ? Wvf : Wpi;
    const float* bias = head ? bvf : bpi;
    int colbase = ct * 64, b0 = bt * 64;

    // pre-dependency: W slice (duplicated) + bias — independent of gnn
    for (int i = t; i < 58 * 64; i += NN) {
        int k = i >> 6, c = i & 63;
        sWd[i] = dup2(W[k * DPI + colbase + c]);
    }
    if (t < 64) sbias[t] = bias[colbase + t];

    cudaGridDependencySynchronize();

    for (int i = t; i < 58 * 32; i += NN) {
        int k = i >> 5, p = i & 31;
        const float* cb = g_comb + (size_t)(b0 + 2 * p) * 64 + k;
        sCp[k * 32 + p] = pack2(cb[0], cb[64]);
    }
    __syncthreads();

    int pg = t & 15, bg = t >> 4;       // cols 4pg..4pg+3; batch pairs 2bg, 2bg+1
    unsigned long long acc[2][4];
#pragma unroll
    for (int c = 0; c < 4; c++) {
        unsigned long long bd = dup2(sbias[4 * pg + c]);
        acc[0][c] = bd; acc[1][c] = bd;
    }

#pragma unroll 2
    for (int k = 0; k < 58; k++) {
        ulonglong2 w01 = *(const ulonglong2*)(sWd + k * 64 + 4 * pg);
        ulonglong2 w23 = *(const ulonglong2*)(sWd + k * 64 + 4 * pg + 2);
        ulonglong2 cp  = *(const ulonglong2*)(sCp + k * 32 + 2 * bg);
        ffma2(acc[0][0], cp.x, w01.x); ffma2(acc[0][1], cp.x, w01.y);
        ffma2(acc[0][2], cp.x, w23.x); ffma2(acc[0][3], cp.x, w23.y);
        ffma2(acc[1][0], cp.y, w01.x); ffma2(acc[1][1], cp.y, w01.y);
        ffma2(acc[1][2], cp.y, w23.x); ffma2(acc[1][3], cp.y, w23.y);
    }

#pragma unroll
    for (int p = 0; p < 2; p++) {
        float l0, h0, l1, h1, l2, h2, l3, h3;
        unpack2(l0, h0, acc[p][0]); unpack2(l1, h1, acc[p][1]);
        unpack2(l2, h2, acc[p][2]); unpack2(l3, h3, acc[p][3]);
        int blo = b0 + 2 * (2 * bg + p);
        size_t base = (size_t)head * BB * DPI + (size_t)blo * DPI + colbase + 4 * pg;
        *(float4*)(out + base) =
            make_float4(fmaxf(l0, 0.f), fmaxf(l1, 0.f), fmaxf(l2, 0.f), fmaxf(l3, 0.f));
        *(float4*)(out + base + DPI) =
            make_float4(fmaxf(h0, 0.f), fmaxf(h1, 0.f), fmaxf(h2, 0.f), fmaxf(h3, 0.f));
    }
}

extern "C" void kernel_launch(void* const* d_in, const int* in_sizes, int n_in,
                              void* d_out, int out_size) {
    const float* gf  = (const float*)d_in[0];
    const float* vec = (const float*)d_in[1];
    const int*   src = (const int*)d_in[2];
    const int*   dst = (const int*)d_in[3];
    const float* W1  = (const float*)d_in[4];
    const float* b1  = (const float*)d_in[5];
    const float* W2  = (const float*)d_in[6];
    const float* b2  = (const float*)d_in[7];
    const float* W3  = (const float*)d_in[8];
    const float* b3  = (const float*)d_in[9];
    const float* We  = (const float*)d_in[10];
    const float* be  = (const float*)d_in[11];
    const float* Wpi = (const float*)d_in[12];
    const float* bpi = (const float*)d_in[13];
    const float* Wvf = (const float*)d_in[14];
    const float* bvf = (const float*)d_in[15];

    int E = in_sizes[2];
    if (E > EMAX) E = EMAX;

    prep1_kernel<<<(E + NN - 1) / NN, NN>>>(src, dst, E);
    prep2_kernel<<<1, NN>>>(src, dst, E);

    // gnn smem floats: 2*9216 + 5136 + 260 + 256 + 192 + 3*1024 + 128 + 512 + 32 = 28020
    int smem = 28020 * (int)sizeof(float);
    cudaFuncSetAttribute(gnn_kernel, cudaFuncAttributeMaxDynamicSharedMemorySize, smem);

    // gnn: PDL-dependent on prep2
    {
        cudaLaunchConfig_t cfg = {};
        cfg.gridDim = dim3(BB, 1, 1);
        cfg.blockDim = dim3(TT, 1, 1);
        cfg.dynamicSmemBytes = (size_t)smem;
        cfg.stream = 0;
        cudaLaunchAttribute attr[1];
        attr[0].id = cudaLaunchAttributeProgrammaticStreamSerialization;
        attr[0].val.programmaticStreamSerializationAllowed = 1;
        cfg.attrs = attr;
        cfg.numAttrs = 1;
        cudaLaunchKernelEx(&cfg, gnn_kernel, gf, vec, W1, b1, W2, b2, W3, b3, We, be);
    }

    // heads: PDL-dependent on gnn
    {
        cudaLaunchConfig_t cfg = {};
        cfg.gridDim = dim3(256, 1, 1);
        cfg.blockDim = dim3(NN, 1, 1);
        cfg.dynamicSmemBytes = 0;
        cfg.stream = 0;
        cudaLaunchAttribute attr[1];
        attr[0].id = cudaLaunchAttributeProgrammaticStreamSerialization;
        attr[0].val.programmaticStreamSerializationAllowed = 1;
        cfg.attrs = attr;
        cfg.numAttrs = 1;
        cudaLaunchKernelEx(&cfg, heads_kernel, Wpi, bpi, Wvf, bvf, (float*)d_out);
    }
}

// round 16
// speedup vs baseline: 1.0493x; 1.0493x over previous
#include <cuda_runtime.h>

#define NN    256
#define TT    512    // gnn CTA threads
#define FIN   6
#define HD    32
#define VECD  26
#define DPI   512
#define BB    1024
#define EMAX  2304
#define EMAXP 2568   // even-padded capacity + zero slots
#define PADJ  2564   // even pair index at guaranteed-zero edges
#define ST    36     // padded row stride (floats)

__device__ int g_degO[NN];
__device__ int g_degI[NN];
__device__ int g_rowptr[NN + 1];
__device__ int g_perm[NN];
__device__ __align__(16) float2 g_edge[EMAXP];
__device__ float g_comb[BB * 64];

// ---------------------------------------------------------------------------
// packed f32x2 helpers
// ---------------------------------------------------------------------------
__device__ __forceinline__ unsigned long long dup2(float v) {
    unsigned long long r;
    asm("mov.b64 %0, {%1, %1};" : "=l"(r) : "f"(v));
    return r;
}
__device__ __forceinline__ unsigned long long pack2(float lo, float hi) {
    unsigned long long r;
    asm("mov.b64 %0, {%1, %2};" : "=l"(r) : "f"(lo), "f"(hi));
    return r;
}
__device__ __forceinline__ void ffma2(unsigned long long& a, unsigned long long x,
                                      unsigned long long y) {
    asm("fma.rn.f32x2 %0, %1, %2, %0;" : "+l"(a) : "l"(x), "l"(y));
}
__device__ __forceinline__ void unpack2(float& lo, float& hi, unsigned long long v) {
    asm("mov.b64 {%0, %1}, %2;" : "=f"(lo), "=f"(hi) : "l"(v));
}

// ---------------------------------------------------------------------------
// prep1: multi-CTA degree histogram (spread global atomics).
// ---------------------------------------------------------------------------
__global__ void prep1_kernel(const int* __restrict__ src, const int* __restrict__ dst, int E) {
    int e = blockIdx.x * blockDim.x + threadIdx.x;
    if (e < E) {
        atomicAdd(&g_degO[src[e]], 1);
        atomicAdd(&g_degI[dst[e]], 1);
    }
}

// ---------------------------------------------------------------------------
// prep2: scan, norms, scatter CSR, counting-sort nodes by padded degree.
// ---------------------------------------------------------------------------
__global__ void prep2_kernel(const int* __restrict__ src, const int* __restrict__ dst, int E) {
    __shared__ float sO[NN], sI[NN];
    __shared__ int cur[NN];
    __shared__ int wsum[8];
    __shared__ int cnt[128];
    int t = threadIdx.x, lane = t & 31, w = t >> 5;
    int dO = g_degO[t], dI = g_degI[t];
    int dp = (dI + 1) & ~1;
    if (t < 128) cnt[t] = 0;
    int v = dp;
#pragma unroll
    for (int o = 1; o < 32; o <<= 1) {
        int nv_ = __shfl_up_sync(0xffffffffu, v, o);
        if (lane >= o) v += nv_;
    }
    if (lane == 31) wsum[w] = v;
    __syncthreads();
    if (t == 0) {
        int acc = 0;
#pragma unroll
        for (int i = 0; i < 8; i++) { acc += wsum[i]; wsum[i] = acc; }
    }
    int bin = dp >> 1; if (bin > 127) bin = 127;
    atomicAdd(&cnt[bin], 1);
    __syncthreads();
    int excl = (w ? wsum[w - 1] : 0) + v - dp;
    g_rowptr[t] = excl;
    cur[t] = excl;
    if (t == NN - 1) g_rowptr[NN] = excl + dp;
    sO[t] = dO ? rsqrtf((float)dO) : 0.f;
    sI[t] = dI ? rsqrtf((float)dI) : 0.f;
    if (t < 32) {
        int c0 = cnt[t*4], c1 = cnt[t*4+1], c2 = cnt[t*4+2], c3 = cnt[t*4+3];
        int tot = c0 + c1 + c2 + c3;
        int sc = tot;
#pragma unroll
        for (int o = 1; o < 32; o <<= 1) {
            int nv_ = __shfl_up_sync(0xffffffffu, sc, o);
            if (lane >= o) sc += nv_;
        }
        int base = sc - tot;
        cnt[t*4]   = base;
        cnt[t*4+1] = base + c0;
        cnt[t*4+2] = base + c0 + c1;
        cnt[t*4+3] = base + c0 + c1 + c2;
    }
    __syncthreads();
    int pos = atomicAdd(&cnt[bin], 1);
    g_perm[pos] = t;
    for (int e = t; e < E; e += NN) {
        int s_ = src[e], d_ = dst[e];
        float nv = sO[s_] * sI[d_];
        int p2 = atomicAdd(&cur[d_], 1);
        g_edge[p2] = make_float2(__int_as_float(s_ * ST), nv);
    }
    if (dI & 1) g_edge[excl + dI] = make_float2(__int_as_float(0), 0.f);
    if (t < 8) g_edge[2560 + t] = make_float2(__int_as_float(0), 0.f);
    g_degO[t] = 0;
    g_degI[t] = 0;
}

// ---------------------------------------------------------------------------
// Octet gather over degree-sorted pairs, edge prefetch pipeline.
// Anti-correlated schedule: thread handles pairs p and 127-p, so every
// thread's degree total is ~constant -> minimal barrier skew.
// ---------------------------------------------------------------------------
template <int POOL>
__device__ __forceinline__ void gatherO(const float* __restrict__ bufS,
                                        float* __restrict__ bufD,
                                        const float* __restrict__ sEf,
                                        const int* __restrict__ srow,
                                        const int* __restrict__ sperm,
                                        const float* __restrict__ sbias,
                                        float* __restrict__ pool, int t)
{
    int l = t & 31, w = t >> 5;
    int o = l >> 3, q = l & 7;
    const float* bufq = bufS + 4 * q;
    float4 bv = *(const float4*)(sbias + 4 * q);
    float4 ps = make_float4(0.f, 0.f, 0.f, 0.f);
    int pbase = w * 4 + o;
#pragma unroll
    for (int pp = 0; pp < 2; pp++) {
        int pair = pp ? (127 - pbase) : pbase;
        int nA = sperm[2 * pair], nB = sperm[2 * pair + 1];
        int jA = srow[nA], eA = srow[nA + 1];
        int jB = srow[nB], eB = srow[nB + 1];
        unsigned long long a0 = 0, a1 = 0, a2 = 0, a3 = 0;
        unsigned long long c0 = 0, c1 = 0, c2 = 0, c3 = 0;
        int iA = jA < eA ? jA : PADJ;
        int iB = jB < eB ? jB : PADJ;
        float4 eA4 = *(const float4*)(sEf + 2 * iA);
        float4 eB4 = *(const float4*)(sEf + 2 * iB);
        while (jA < eA || jB < eB) {
            float4 cA = eA4, cB = eB4;
            jA += 2; jB += 2;
            iA = jA < eA ? jA : PADJ;
            iB = jB < eB ? jB : PADJ;
            eA4 = *(const float4*)(sEf + 2 * iA);
            eB4 = *(const float4*)(sEf + 2 * iB);
            ulonglong2 xA0 = *(const ulonglong2*)(bufq + __float_as_int(cA.x));
            ulonglong2 xA1 = *(const ulonglong2*)(bufq + __float_as_int(cA.z));
            ulonglong2 xB0 = *(const ulonglong2*)(bufq + __float_as_int(cB.x));
            ulonglong2 xB1 = *(const ulonglong2*)(bufq + __float_as_int(cB.z));
            unsigned long long vA0 = dup2(cA.y), vA1 = dup2(cA.w);
            unsigned long long vB0 = dup2(cB.y), vB1 = dup2(cB.w);
            ffma2(a0, vA0, xA0.x); ffma2(a1, vA0, xA0.y);
            ffma2(a2, vA1, xA1.x); ffma2(a3, vA1, xA1.y);
            ffma2(c0, vB0, xB0.x); ffma2(c1, vB0, xB0.y);
            ffma2(c2, vB1, xB1.x); ffma2(c3, vB1, xB1.y);
        }
        float r0, r1, r2, r3, s0, s1, s2, s3;
        unpack2(r0, r1, a0); unpack2(r2, r3, a1);
        unpack2(s0, s1, a2); unpack2(s2, s3, a3);
        float4 hA;
        hA.x = fmaxf(r0 + s0 + bv.x, 0.f);
        hA.y = fmaxf(r1 + s1 + bv.y, 0.f);
        hA.z = fmaxf(r2 + s2 + bv.z, 0.f);
        hA.w = fmaxf(r3 + s3 + bv.w, 0.f);
        unpack2(r0, r1, c0); unpack2(r2, r3, c1);
        unpack2(s0, s1, c2); unpack2(s2, s3, c3);
        float4 hB;
        hB.x = fmaxf(r0 + s0 + bv.x, 0.f);
        hB.y = fmaxf(r1 + s1 + bv.y, 0.f);
        hB.z = fmaxf(r2 + s2 + bv.z, 0.f);
        hB.w = fmaxf(r3 + s3 + bv.w, 0.f);
        if (POOL) {
            ps.x += hA.x + hB.x; ps.y += hA.y + hB.y;
            ps.z += hA.z + hB.z; ps.w += hA.w + hB.w;
        } else {
            *(float4*)(bufD + nA * ST + 4 * q) = hA;
            *(float4*)(bufD + nB * ST + 4 * q) = hB;
        }
    }
    if (POOL) {
#pragma unroll
        for (int m = 8; m <= 16; m <<= 1) {
            ps.x += __shfl_xor_sync(0xffffffffu, ps.x, m);
            ps.y += __shfl_xor_sync(0xffffffffu, ps.y, m);
            ps.z += __shfl_xor_sync(0xffffffffu, ps.z, m);
            ps.w += __shfl_xor_sync(0xffffffffu, ps.w, m);
        }
        if (l < 8) *(float4*)(pool + (w * 8 + q) * 4) = ps;
    }
}

// ---------------------------------------------------------------------------
// Linear: thread = (node t>>1, feature-half t&1); 16 outputs via f32x2.
// ---------------------------------------------------------------------------
__device__ __forceinline__ void linear_phase(const float* __restrict__ bufS,
                                             float* __restrict__ bufD,
                                             const float* __restrict__ W, int t)
{
    int n = t >> 1, fo = (t & 1) * 16;
    float h[HD];
    const float4* hr = (const float4*)(bufS + n * ST);
#pragma unroll
    for (int q = 0; q < 8; q++) {
        float4 v = hr[q];
        h[4*q] = v.x; h[4*q+1] = v.y; h[4*q+2] = v.z; h[4*q+3] = v.w;
    }
    unsigned long long y2[8];
#pragma unroll
    for (int q = 0; q < 8; q++) y2[q] = 0ULL;
#pragma unroll
    for (int k = 0; k < HD; k++) {
        unsigned long long hk = dup2(h[k]);
        const ulonglong2* Wr = (const ulonglong2*)(W + k * HD + fo);
#pragma unroll
        for (int q = 0; q < 4; q++) {
            ulonglong2 wv = Wr[q];
            ffma2(y2[2*q],     hk, wv.x);
            ffma2(y2[2*q + 1], hk, wv.y);
        }
    }
    ulonglong2* out = (ulonglong2*)(bufD + n * ST + fo);
#pragma unroll
    for (int q = 0; q < 4; q++) out[q] = make_ulonglong2(y2[2*q], y2[2*q+1]);
}

// ---------------------------------------------------------------------------
// Main GNN kernel: one CTA (512 threads) per batch element.
// ---------------------------------------------------------------------------
__global__ void __launch_bounds__(TT, 2) gnn_kernel(
    const float* __restrict__ gf, const float* __restrict__ vec,
    const float* __restrict__ W1, const float* __restrict__ b1,
    const float* __restrict__ W2, const float* __restrict__ b2,
    const float* __restrict__ W3, const float* __restrict__ b3,
    const float* __restrict__ We, const float* __restrict__ be)
{
    extern __shared__ float s[];
    float* bufA = s;                         // 9216
    float* bufB = bufA + NN * ST;            // 9216
    float* sEf  = bufB + NN * ST;            // 5136
    int*   srow = (int*)(sEf + 2 * EMAXP);   // 260
    int*   sperm= srow + 260;                // 256
    float* sW1  = (float*)(sperm + 256);     // 192
    float* sW2  = sW1 + 192;                 // 1024
    float* sW3  = sW2 + 1024;                // 1024
    float* sWe  = sW3 + 1024;                // 1024
    float* sb   = sWe + 1024;                // 128
    float* pool = sb + 128;                  // 512
    float* hg   = pool + 512;                // 32

    int t = threadIdx.x;
    int b = blockIdx.x;

    // ---- stage CSR, perm, weights, gf ----
    {
        const float4* ge4 = (const float4*)g_edge;
        float4* se4 = (float4*)sEf;
        for (int i = t; i < EMAXP / 2; i += TT) se4[i] = ge4[i];
        if (t < NN) { srow[t] = g_rowptr[t]; sperm[t] = g_perm[t]; }
        if (t == 0) srow[NN] = g_rowptr[NN];
        if (t < FIN * HD) sW1[t] = W1[t];
        for (int i = t; i < HD * HD; i += TT) {
            sW2[i] = W2[i]; sW3[i] = W3[i]; sWe[i] = We[i];
        }
        if (t < HD) { sb[t] = b1[t]; sb[32+t] = b2[t]; sb[64+t] = b3[t]; sb[96+t] = be[t]; }
        const float4* g4 = (const float4*)(gf + (size_t)b * NN * FIN);
        float4* xb = (float4*)bufB;
        if (t < NN * FIN / 4) xb[t] = g4[t];
    }
    __syncthreads();

    // ---- phase 0: t0 = x @ W1 -> bufA (node t>>1, 16 features) ----
    {
        int n = t >> 1, fo = (t & 1) * 16;
        float x[FIN];
#pragma unroll
        for (int k = 0; k < FIN; k++) x[k] = bufB[n * FIN + k];
        unsigned long long y2[8];
#pragma unroll
        for (int q = 0; q < 8; q++) y2[q] = 0ULL;
#pragma unroll
        for (int k = 0; k < FIN; k++) {
            unsigned long long xk = dup2(x[k]);
            const ulonglong2* Wr = (const ulonglong2*)(sW1 + k * HD + fo);
#pragma unroll
            for (int q = 0; q < 4; q++) {
                ulonglong2 wv = Wr[q];
                ffma2(y2[2*q], xk, wv.x);
                ffma2(y2[2*q+1], xk, wv.y);
            }
        }
        ulonglong2* row = (ulonglong2*)(bufA + n * ST + fo);
#pragma unroll
        for (int q = 0; q < 4; q++) row[q] = make_ulonglong2(y2[2*q], y2[2*q+1]);
    }
    __syncthreads();

    gatherO<0>(bufA, bufB, sEf, srow, sperm, sb, pool, t);
    __syncthreads();
    linear_phase(bufB, bufA, sW2, t);
    __syncthreads();
    gatherO<0>(bufA, bufB, sEf, srow, sperm, sb + 32, pool, t);
    __syncthreads();
    linear_phase(bufB, bufA, sW3, t);
    __syncthreads();
    gatherO<1>(bufA, bufB, sEf, srow, sperm, sb + 64, pool, t);
    __syncthreads();

    // ---- finish mean pool (16 warps' partials) ----
    if (t < 8) {
        float4 sum = make_float4(0.f, 0.f, 0.f, 0.f);
#pragma unroll
        for (int w = 0; w < 16; w++) {
            float4 v = *(const float4*)(pool + (w * 8 + t) * 4);
            sum.x += v.x; sum.y += v.y; sum.z += v.z; sum.w += v.w;
        }
        const float inv = 1.f / 256.f;
        hg[4*t]   = sum.x * inv; hg[4*t+1] = sum.y * inv;
        hg[4*t+2] = sum.z * inv; hg[4*t+3] = sum.w * inv;
    }
    __syncthreads();

    if (t < HD) {
        float e = sb[96 + t];
#pragma unroll
        for (int k = 0; k < HD; k++)
            e = fmaf(hg[k], sWe[k * HD + t], e);
        g_comb[b * 64 + VECD + t] = e;
    }
    if (t >= 64 && t < 64 + VECD)
        g_comb[b * 64 + (t - 64)] = vec[(size_t)b * VECD + (t - 64)];
}

// ---------------------------------------------------------------------------
// Heads: grid 256 = 16 batch-tiles(64) x 8 col-tiles(64) x 2 heads.
// Thread: 2 batch-pairs (4 batches) x 4 cols; per k: 1 LDS.128 W +
// 1 LDS.128 C-pairs + 4 dup + 8 FFMA2. ~30KB smem.
// ---------------------------------------------------------------------------
__global__ void __launch_bounds__(NN) heads_kernel(
    const float* __restrict__ Wpi, const float* __restrict__ bpi,
    const float* __restrict__ Wvf, const float* __restrict__ bvf,
    float* __restrict__ out)
{
    __shared__ __align__(16) float sW[58 * 64];
    __shared__ unsigned long long sCp[58 * 32];
    __shared__ float sbias[64];

    int t = threadIdx.x;
    int bt = blockIdx.x & 15;
    int ct = (blockIdx.x >> 4) & 7;
    int head = blockIdx.x >> 7;
    const float* W = head ? Wvf : Wpi;
    const float* bias = head ? bvf : bpi;
    int colbase = ct * 64, b0 = bt * 64;

    for (int i = t; i < 58 * 16; i += NN) {
        int k = i >> 4, c = i & 15;
        *(float4*)(sW + k * 64 + c * 4) = *(const float4*)(W + k * DPI + colbase + c * 4);
    }
    if (t < 64) sbias[t] = bias[colbase + t];
    for (int i = t; i < 58 * 32; i += NN) {
        int k = i >> 5, p = i & 31;
        const float* cb = g_comb + (size_t)(b0 + 2 * p) * 64 + k;
        sCp[k * 32 + p] = pack2(cb[0], cb[64]);
    }
    __syncthreads();

    int pg = t & 15, bg = t >> 4;       // cols 4pg..4pg+3; batch pairs 2bg, 2bg+1
    unsigned long long acc[2][4];
#pragma unroll
    for (int c = 0; c < 4; c++) {
        unsigned long long bd = dup2(sbias[4 * pg + c]);
        acc[0][c] = bd; acc[1][c] = bd;
    }

#pragma unroll 2
    for (int k = 0; k < 58; k++) {
        float4 wv = *(const float4*)(sW + k * 64 + 4 * pg);
        ulonglong2 cp = *(const ulonglong2*)(sCp + k * 32 + 2 * bg);
        unsigned long long w0 = dup2(wv.x), w1 = dup2(wv.y),
                           w2 = dup2(wv.z), w3 = dup2(wv.w);
        ffma2(acc[0][0], cp.x, w0); ffma2(acc[0][1], cp.x, w1);
        ffma2(acc[0][2], cp.x, w2); ffma2(acc[0][3], cp.x, w3);
        ffma2(acc[1][0], cp.y, w0); ffma2(acc[1][1], cp.y, w1);
        ffma2(acc[1][2], cp.y, w2); ffma2(acc[1][3], cp.y, w3);
    }

#pragma unroll
    for (int p = 0; p < 2; p++) {
        float l0, h0, l1, h1, l2, h2, l3, h3;
        unpack2(l0, h0, acc[p][0]); unpack2(l1, h1, acc[p][1]);
        unpack2(l2, h2, acc[p][2]); unpack2(l3, h3, acc[p][3]);
        int blo = b0 + 2 * (2 * bg + p);
        size_t base = (size_t)head * BB * DPI + (size_t)blo * DPI + colbase + 4 * pg;
        *(float4*)(out + base) =
            make_float4(fmaxf(l0, 0.f), fmaxf(l1, 0.f), fmaxf(l2, 0.f), fmaxf(l3, 0.f));
        *(float4*)(out + base + DPI) =
            make_float4(fmaxf(h0, 0.f), fmaxf(h1, 0.f), fmaxf(h2, 0.f), fmaxf(h3, 0.f));
    }
}

extern "C" void kernel_launch(void* const* d_in, const int* in_sizes, int n_in,
                              void* d_out, int out_size) {
    const float* gf  = (const float*)d_in[0];
    const float* vec = (const float*)d_in[1];
    const int*   src = (const int*)d_in[2];
    const int*   dst = (const int*)d_in[3];
    const float* W1  = (const float*)d_in[4];
    const float* b1  = (const float*)d_in[5];
    const float* W2  = (const float*)d_in[6];
    const float* b2  = (const float*)d_in[7];
    const float* W3  = (const float*)d_in[8];
    const float* b3  = (const float*)d_in[9];
    const float* We  = (const float*)d_in[10];
    const float* be  = (const float*)d_in[11];
    const float* Wpi = (const float*)d_in[12];
    const float* bpi = (const float*)d_in[13];
    const float* Wvf = (const float*)d_in[14];
    const float* bvf = (const float*)d_in[15];

    int E = in_sizes[2];
    if (E > EMAX) E = EMAX;

    prep1_kernel<<<(E + NN - 1) / NN, NN>>>(src, dst, E);
    prep2_kernel<<<1, NN>>>(src, dst, E);

    // gnn smem floats: 2*9216 + 5136 + 260 + 256 + 192 + 3*1024 + 128 + 512 + 32 = 28020
    int smem = 28020 * (int)sizeof(float);
    cudaFuncSetAttribute(gnn_kernel, cudaFuncAttributeMaxDynamicSharedMemorySize, smem);
    gnn_kernel<<<BB, TT, smem>>>(gf, vec, W1, b1, W2, b2, W3, b3, We, be);

    heads_kernel<<<256, NN>>>(Wpi, bpi, Wvf, bvf, (float*)d_out);
}